// round 14
// baseline (speedup 1.0000x reference)
#include <cuda_runtime.h>
#include <cuda_bf16.h>
#include <cstdint>

#define B      512
#define DIM    128
#define MARGIN 0.2f
#define EPSF   1e-6f
#define BIGF   1e30f
#define SENTTH 1e29f
#define FULLM  0xffffffffu

#define LDU 132          // u row stride (floats)
#define LDC 20           // chunk-buffer row stride (floats): 16 dims + 4 pad
#define LDD 516          // D slab row stride (floats)
#define NT  512          // threads per block
#define NCH 8            // d-chunks of 16 dims
#define ROWS_PER_BLK 2
#define GRID (B / ROWS_PER_BLK)   // 256 blocks -> 2 co-resident per SM

// Accumulators (allocation-free rule). Statics init to zero; the last block
// resets them after use, so every graph replay starts from zero.
__device__ double g_num = 0.0;
__device__ unsigned long long g_den = 0ull;
__device__ unsigned int g_done = 0u;

static __device__ __forceinline__ unsigned smem_u32(const void* p) {
    return (unsigned)__cvta_generic_to_shared(p);
}

#define FMA2(acc, a, b) \
    asm volatile("fma.rn.f32x2 %0, %1, %2, %0;" : "+l"(acc) : "l"(a), "l"(b))
#define LDS_V2B64(lo, hi, addr) \
    asm volatile("ld.shared.v2.b64 {%0, %1}, [%2];" : "=l"(lo), "=l"(hi) : "r"(addr))

static __device__ __forceinline__ float hadd_f32x2(uint64_t p) {
    float lo, hi;
    asm volatile("mov.b64 {%0, %1}, %2;" : "=f"(lo), "=f"(hi) : "l"(p));
    return lo + hi;
}

// ---------------------------------------------------------------------------
// ONE fused kernel, 512 threads, 2 blocks co-resident per SM (87KB smem,
// launch_bounds(512,2)). Block b = anchor rows [2b, 2b+2).
// Phase A: thread tid owns j-column tid for both anchors. 8 d-chunks of 16
//   dims, double-buffered cp.async. No cross-thread combine.
// Phase B (warps 0-1): register-resident bitonic sort per row (R6-verified),
//   LSB tag + closed-form prefix, single atomic finalize.
// ---------------------------------------------------------------------------
__global__ __launch_bounds__(NT, 2) void fused_kernel(const float* __restrict__ F,
                                                      const int* __restrict__ mask,
                                                      float* __restrict__ out) {
    extern __shared__ float sm[];
    float* u_s  = sm;                          //   2 * 132
    float* Fc_s = u_s + 2 * LDU;               // 2 * 512 * 20 (chunk buffers)
    float* D_s  = Fc_s + 2 * B * LDC;          //   2 * 516
    float* s_ni = D_s + 2 * LDD;               //   2
    float* s_bs = s_ni + 2;                    //   2
    unsigned long long* s_bd = (unsigned long long*)(s_bs + 2);   // 2

    const int tid  = threadIdx.x;
    const int lane = tid & 31;
    const int warp = tid >> 5;
    const int i0   = blockIdx.x * ROWS_PER_BLK;

    // ---- prefetch mask row for my sort row (warps 0-1) ----------------------
    int4 m4p[4];
    if (warp < ROWS_PER_BLK) {
        const int4* Mrow = (const int4*)(mask + (i0 + warp) * B);
#pragma unroll
        for (int qq = 0; qq < 4; qq++) m4p[qq] = Mrow[lane * 4 + qq];
    }

    // ---- stage u = f(anchor rows) + eps (first 256 threads) ------------------
    if (tid < ROWS_PER_BLK * DIM) {
        const int r = tid >> 7, d = tid & 127;
        u_s[r * LDU + d] = F[(i0 + r) * DIM + d] + EPSF;
    }

    // ---- cp.async staging: chunk c (16 dims, all 512 rows) -> buffer c&1 -----
    // 512 rows x 16 floats = 2048 granules of 16B; 4 per thread.
#define CP_CHUNK(C)                                                            \
    {                                                                          \
        const int buf = (C) & 1;                                               \
        _Pragma("unroll")                                                      \
        for (int k = 0; k < 4; k++) {                                          \
            const int g   = tid + (k << 9);                                    \
            const int row = g >> 2;                                            \
            const int sub = g & 3;                                             \
            const unsigned dst =                                               \
                smem_u32(&Fc_s[buf * B * LDC + row * LDC + sub * 4]);          \
            const float* src = F + row * DIM + (C) * 16 + sub * 4;             \
            asm volatile("cp.async.cg.shared.global [%0], [%1], 16;"           \
                         :: "r"(dst), "l"(src));                               \
        }                                                                      \
        asm volatile("cp.async.commit_group;");                                \
    }

    CP_CHUNK(0)
    CP_CHUNK(1)

    __syncthreads();   // u_s visible

    // ---- |u_i|^2 (warps 0-1; warp w -> row w) --------------------------------
    if (warp < ROWS_PER_BLK) {
        float s = 0.f;
#pragma unroll
        for (int qq = 0; qq < 4; qq++) {
            const float x = u_s[warp * LDU + lane + 32 * qq];
            s = fmaf(x, x, s);
        }
#pragma unroll
        for (int off = 16; off; off >>= 1) s += __shfl_down_sync(FULLM, s, off);
        if (lane == 0) s_ni[warp] = s;
    }

    // ---- Phase A: 8 d-chunks, double-buffered --------------------------------
    uint64_t A0 = 0ull, A1 = 0ull, NF2 = 0ull;
    const unsigned ub  = smem_u32(u_s);
    const unsigned fcb = smem_u32(Fc_s);

#pragma unroll
    for (int c = 0; c < NCH; c++) {
        if (c < NCH - 1) asm volatile("cp.async.wait_group 1;");
        else             asm volatile("cp.async.wait_group 0;");
        __syncthreads();   // chunk c visible to all threads

        const unsigned fb  = fcb + ((unsigned)(c & 1) * B * LDC + tid * LDC) * 4u;
        const unsigned uc0 = ub + 0 * (LDU * 4) + c * 64u;   // c*16 floats
        const unsigned uc1 = ub + 1 * (LDU * 4) + c * 64u;
#pragma unroll
        for (int dq = 0; dq < 4; dq++) {
            uint64_t f0, f1, x0, x1;
            LDS_V2B64(f0, f1, fb + 16 * dq);
            FMA2(NF2, f0, f0);
            FMA2(NF2, f1, f1);
            LDS_V2B64(x0, x1, uc0 + 16 * dq);
            FMA2(A0, x0, f0);
            FMA2(A0, x1, f1);
            LDS_V2B64(x0, x1, uc1 + 16 * dq);
            FMA2(A1, x0, f0);
            FMA2(A1, x1, f1);
        }
        __syncthreads();   // all threads done reading buffer c&1
        if (c + 2 < NCH) CP_CHUNK(c + 2)
    }

    // ---- epilogue: D row slab (thread owns its column) -----------------------
    {
        const float a0 = hadd_f32x2(A0);
        const float a1 = hadd_f32x2(A1);
        const float nf = hadd_f32x2(NF2);
        D_s[0 * LDD + tid] = sqrtf(fmaxf(s_ni[0] + nf - 2.f * a0, 0.f));
        D_s[1 * LDD + tid] = sqrtf(fmaxf(s_ni[1] + nf - 2.f * a1, 0.f));
    }
    __syncthreads();   // D_s complete

    // =========================================================================
    // Phase B (warps 0-1): register-resident sort of row i0+warp (R6-verified).
    // Element e = lane*16 + r. LSB tag: pos=(d+margin)|1, neg=d&~1,
    // excluded diagonal = BIGF (value-guarded out of float sums).
    // =========================================================================
    if (warp < ROWS_PER_BLK) {
        const int i = i0 + warp;
        float v[16];
        int npos = 0, nneg = 0;

#pragma unroll
        for (int qq = 0; qq < 4; qq++) {
            const float4 d4 = *(const float4*)&D_s[warp * LDD + lane * 16 + 4 * qq];
            const float dv[4] = {d4.x, d4.y, d4.z, d4.w};
            const int   mv[4] = {m4p[qq].x, m4p[qq].y, m4p[qq].z, m4p[qq].w};
#pragma unroll
            for (int t = 0; t < 4; t++) {
                const int j = lane * 16 + qq * 4 + t;
                unsigned kb;
                if (mv[t] != 0) {
                    kb = __float_as_uint(dv[t] + MARGIN) | 1u;
                    npos++;
                } else if (j == i) {
                    kb = __float_as_uint(BIGF) & ~1u;
                } else {
                    kb = __float_as_uint(dv[t]) & ~1u;
                    nneg++;
                }
                v[qq * 4 + t] = __uint_as_float(kb);
            }
        }
        const int np = __reduce_add_sync(FULLM, npos);
        const int nn = __reduce_add_sync(FULLM, nneg);

        // bitonic sort of 512 keys, ascending (register + shfl only)
#pragma unroll
        for (int k = 2; k <= 512; k <<= 1) {
            const bool asc_lane_valid = (k >= 16);
            const bool asc_l = ((lane & (k >> 4)) == 0);
#pragma unroll
            for (int j = k >> 1; j >= 1; j >>= 1) {
                if (j >= 16) {
                    const int jl2 = j >> 4;
                    const bool keep_min = (((lane & jl2) == 0) == asc_l);
#pragma unroll
                    for (int r = 0; r < 16; r++) {
                        const float pv = __shfl_xor_sync(FULLM, v[r], jl2);
                        v[r] = keep_min ? fminf(v[r], pv) : fmaxf(v[r], pv);
                    }
                } else {
#pragma unroll
                    for (int r = 0; r < 16; r++) {
                        if ((r & j) == 0) {
                            const int r2 = r | j;
                            const bool asc = asc_lane_valid ? asc_l : ((r & k) == 0);
                            const float a = v[r], bb = v[r2];
                            const float lo = fminf(a, bb), hi = fmaxf(a, bb);
                            v[r]  = asc ? lo : hi;
                            v[r2] = asc ? hi : lo;
                        }
                    }
                }
            }
        }

        // pass 1: per-lane negative (sum, count), sentinel value-guarded
        float runs = 0.f;
        int   runc = 0;
#pragma unroll
        for (int r = 0; r < 16; r++) {
            const bool isneg = ((__float_as_uint(v[r]) & 1u) == 0) && (v[r] < SENTTH);
            if (isneg) { runs += v[r]; runc++; }
        }
        float ls = runs;
        int   lc = runc;
#pragma unroll
        for (int off = 1; off < 32; off <<= 1) {
            const float y = __shfl_up_sync(FULLM, ls, off);
            const int   z = __shfl_up_sync(FULLM, lc, off);
            if (lane >= off) { ls += y; lc += z; }
        }
        float rs = ls - runs;
        int   rc = lc - runc;

        // pass 2: positive contributions
        float local = 0.f;
#pragma unroll
        for (int r = 0; r < 16; r++) {
            const bool ispos = (__float_as_uint(v[r]) & 1u) != 0;
            if (ispos) {
                local += (float)rc * v[r] - rs;
            } else if (v[r] < SENTTH) {
                rs += v[r];
                rc++;
            }
        }

#pragma unroll
        for (int off = 16; off; off >>= 1)
            local += __shfl_down_sync(FULLM, local, off);

        if (lane == 0) {
            s_bs[warp] = local;
            s_bd[warp] = (unsigned long long)np * (unsigned long long)nn;
        }
    }
    __syncthreads();

    if (tid == 0) {
        const float s = s_bs[0] + s_bs[1];
        const unsigned long long d = s_bd[0] + s_bd[1];
        atomicAdd(&g_num, (double)s);
        atomicAdd(&g_den, d);
        __threadfence();
        const unsigned int ticket = atomicAdd(&g_done, 1u);
        if (ticket == gridDim.x - 1) {
            const double num = atomicAdd(&g_num, 0.0);
            const unsigned long long den = atomicAdd(&g_den, 0ull);
            out[0] = (den > 0ull) ? (float)(num / (double)den) : 0.0f;
            g_num  = 0.0;
            g_den  = 0ull;
            __threadfence();
            g_done = 0u;
        }
    }
}

// ---------------------------------------------------------------------------
extern "C" void kernel_launch(void* const* d_in, const int* in_sizes, int n_in,
                              void* d_out, int out_size) {
    const float* features = (const float*)d_in[0];   // [512,128] f32
    const int*   mask     = (const int*)d_in[1];     // [512,512] i32
    float* out = (float*)d_out;

    const int smem_bytes =
        (2 * LDU + 2 * B * LDC + 2 * LDD + 2 + 2) * (int)sizeof(float)
        + 2 * (int)sizeof(unsigned long long);
    static bool attr_set = false;
    if (!attr_set) {
        cudaFuncSetAttribute(fused_kernel, cudaFuncAttributeMaxDynamicSharedMemorySize,
                             smem_bytes);
        attr_set = true;
    }

    fused_kernel<<<GRID, NT, smem_bytes>>>(features, mask, out);
}

// round 15
// speedup vs baseline: 1.3563x; 1.3563x over previous
#include <cuda_runtime.h>
#include <cuda_bf16.h>
#include <cstdint>

#define B      512
#define DIM    128
#define MARGIN 0.2f
#define EPSF   1e-6f
#define BIGF   1e30f
#define SENTTH 1e29f
#define FULLM  0xffffffffu

#define LDJ 132
#define LDD 516
#define TJ  256
#define NT  512

__device__ double g_num = 0.0;
__device__ unsigned long long g_den = 0ull;
__device__ unsigned int g_done = 0u;

static __device__ __forceinline__ unsigned smem_u32(const void* p) {
    return (unsigned)__cvta_generic_to_shared(p);
}
#define FMA2(acc, a, b) \
    asm volatile("fma.rn.f32x2 %0, %1, %2, %0;" : "+l"(acc) : "l"(a), "l"(b))
#define LDS_V2B64(lo, hi, addr) \
    asm volatile("ld.shared.v2.b64 {%0, %1}, [%2];" : "=l"(lo), "=l"(hi) : "r"(addr))
static __device__ __forceinline__ float hadd_f32x2(uint64_t p) {
    float lo, hi;
    asm volatile("mov.b64 {%0, %1}, %2;" : "=f"(lo), "=f"(hi) : "l"(p));
    return lo + hi;
}

// ---- 4-warp cooperative bitonic helpers (group = 128 threads, 4 keys/thread)
#define GBAR() asm volatile("bar.sync %0, 128;" :: "r"(g + 1) : "memory")

#define CMPX(a, b, ASC) {                                                     \
    const float lo = fminf(v[a], v[b]), hi = fmaxf(v[a], v[b]);               \
    v[a] = (ASC) ? lo : hi; v[b] = (ASC) ? hi : lo; }

#define SHFL_ST(JL, ASC) {                                                    \
    const bool km = (((lane & (JL)) == 0) == (ASC));                          \
    _Pragma("unroll")                                                         \
    for (int r = 0; r < 4; r++) {                                             \
        const float p = __shfl_xor_sync(FULLM, v[r], (JL));                   \
        v[r] = km ? fminf(v[r], p) : fmaxf(v[r], p);                          \
    } }

#define SMEM_ST(JT, ASC, LEAD) {                                              \
    if (LEAD) GBAR();                                                         \
    *(float4*)&D_s[g * LDD + t * 4] = make_float4(v[0], v[1], v[2], v[3]);    \
    GBAR();                                                                   \
    const float4 pv = *(const float4*)&D_s[g * LDD + (t ^ (JT)) * 4];         \
    const bool km = (((t & (JT)) == 0) == (ASC));                             \
    v[0] = km ? fminf(v[0], pv.x) : fmaxf(v[0], pv.x);                        \
    v[1] = km ? fminf(v[1], pv.y) : fmaxf(v[1], pv.y);                        \
    v[2] = km ? fminf(v[2], pv.z) : fmaxf(v[2], pv.z);                        \
    v[3] = km ? fminf(v[3], pv.w) : fmaxf(v[3], pv.w); }

// ---------------------------------------------------------------------------
__global__ __launch_bounds__(NT) void fused_kernel(const float* __restrict__ F,
                                                   const int* __restrict__ mask,
                                                   float* __restrict__ out) {
    extern __shared__ float sm[];
    float* u_s    = sm;                        //   4 * 132
    float* Fj_s   = u_s + 4 * LDJ;             // 256 * 132
    float* D_s    = Fj_s + TJ * LDJ;           //   4 * 516 (doubles as sort scratch)
    float* s_ni   = D_s + 4 * LDD;             //   4
    float* s_part = s_ni + 4;                  // 256 * 6
    float* s_wt   = s_part + 256 * 6;          //  16 (warp scan totals: sum)
    int*   s_wc   = (int*)(s_wt + 16);         //  16 (warp scan totals: count)
    int*   s_np   = s_wc + 16;                 //  16
    int*   s_nn   = s_np + 16;                 //  16
    float* s_bs   = (float*)(s_nn + 16);       //  16

    const int tid  = threadIdx.x;
    const int lane = tid & 31;
    const int warp = tid >> 5;
    const int i0   = blockIdx.x * 4;
    const int h    = tid >> 8;        // d-half for phase A
    const int jl   = tid & 255;       // j column within tile
    const int g    = warp >> 2;       // sort group = row
    const int wg   = warp & 3;        // warp within group
    const int t    = wg * 32 + lane;  // thread index within group

    // ---- prefetch mask quad for my sort elements (all warps) ----------------
    const int4 m4 = ((const int4*)(mask + (i0 + g) * B))[t];

    // ---- stage u = f(anchor rows) + eps --------------------------------------
    for (int idx = tid; idx < 4 * DIM; idx += NT) {
        const int r = idx >> 7, d = idx & 127;
        u_s[r * LDJ + d] = F[(i0 + r) * DIM + d] + EPSF;
    }
    __syncthreads();

    // ---- |u_i|^2 (warps 0-3; warp w -> row w) --------------------------------
    if (warp < 4) {
        float s = 0.f;
#pragma unroll
        for (int qq = 0; qq < 4; qq++) {
            const float x = u_s[warp * LDJ + lane + 32 * qq];
            s = fmaf(x, x, s);
        }
#pragma unroll
        for (int off = 16; off; off >>= 1) s += __shfl_down_sync(FULLM, s, off);
        if (lane == 0) s_ni[warp] = s;
    }

    const float4* F4 = (const float4*)F;
    const unsigned u0a = smem_u32(&u_s[0 * LDJ + 64 * h]);
    const unsigned u1a = smem_u32(&u_s[1 * LDJ + 64 * h]);
    const unsigned u2a = smem_u32(&u_s[2 * LDJ + 64 * h]);
    const unsigned u3a = smem_u32(&u_s[3 * LDJ + 64 * h]);
    const unsigned fja = smem_u32(&Fj_s[jl * LDJ + 64 * h]);

    // ---- Phase A (identical to R12 best): 2 j-tiles of 256, f32x2 inner -----
#pragma unroll
    for (int p = 0; p < 2; p++) {
        __syncthreads();
#pragma unroll
        for (int k = 0; k < 16; k++) {
            const int idx = tid + (k << 9);
            const int r = idx >> 5, c = idx & 31;
            const float4 fv = F4[(TJ * p + r) * 32 + c];
            *(float4*)&Fj_s[r * LDJ + 4 * c] = fv;
        }
        __syncthreads();

        uint64_t A0 = 0ull, A1 = 0ull, A2 = 0ull, A3 = 0ull, NF2 = 0ull;
#pragma unroll
        for (int dq = 0; dq < 16; dq++) {
            uint64_t f0, f1, x0, x1;
            LDS_V2B64(f0, f1, fja + 16 * dq);
            FMA2(NF2, f0, f0);
            FMA2(NF2, f1, f1);
            LDS_V2B64(x0, x1, u0a + 16 * dq);
            FMA2(A0, x0, f0);
            FMA2(A0, x1, f1);
            LDS_V2B64(x0, x1, u1a + 16 * dq);
            FMA2(A1, x0, f0);
            FMA2(A1, x1, f1);
            LDS_V2B64(x0, x1, u2a + 16 * dq);
            FMA2(A2, x0, f0);
            FMA2(A2, x1, f1);
            LDS_V2B64(x0, x1, u3a + 16 * dq);
            FMA2(A3, x0, f0);
            FMA2(A3, x1, f1);
        }
        const float a0 = hadd_f32x2(A0);
        const float a1 = hadd_f32x2(A1);
        const float a2 = hadd_f32x2(A2);
        const float a3 = hadd_f32x2(A3);
        const float nf = hadd_f32x2(NF2);

        if (h == 1) {
            float* dst = &s_part[jl * 6];
            dst[0] = a0; dst[1] = a1; dst[2] = a2; dst[3] = a3; dst[4] = nf;
        }
        __syncthreads();
        if (h == 0) {
            const float* src = &s_part[jl * 6];
            const float B0 = a0 + src[0];
            const float B1 = a1 + src[1];
            const float B2 = a2 + src[2];
            const float B3 = a3 + src[3];
            const float NF = nf + src[4];
            const int jc = p * TJ + jl;
            D_s[0 * LDD + jc] = sqrtf(fmaxf(s_ni[0] + NF - 2.f * B0, 0.f));
            D_s[1 * LDD + jc] = sqrtf(fmaxf(s_ni[1] + NF - 2.f * B1, 0.f));
            D_s[2 * LDD + jc] = sqrtf(fmaxf(s_ni[2] + NF - 2.f * B2, 0.f));
            D_s[3 * LDD + jc] = sqrtf(fmaxf(s_ni[3] + NF - 2.f * B3, 0.f));
        }
    }
    __syncthreads();   // D_s complete

    // =========================================================================
    // Phase B: ALL 16 warps. Group g (4 warps) sorts row i0+g cooperatively.
    // Thread owns elements e = t*4 + r. LSB tag as before; sentinel guarded.
    // =========================================================================
    float v[4];
    int npos = 0, nneg = 0;
    {
        const float4 d4 = *(const float4*)&D_s[g * LDD + t * 4];
        const float dv[4] = {d4.x, d4.y, d4.z, d4.w};
        const int   mv[4] = {m4.x, m4.y, m4.z, m4.w};
        const int   i     = i0 + g;
#pragma unroll
        for (int r = 0; r < 4; r++) {
            const int j = t * 4 + r;
            unsigned kb;
            if (mv[r] != 0) {
                kb = __float_as_uint(dv[r] + MARGIN) | 1u;
                npos++;
            } else if (j == i) {
                kb = __float_as_uint(BIGF) & ~1u;
            } else {
                kb = __float_as_uint(dv[r]) & ~1u;
                nneg++;
            }
            v[r] = __uint_as_float(kb);
        }
    }

    // ---- cooperative bitonic sort, ascending over e = t*4 + r ---------------
    // direction for k>=8: asc = ((t & (k>>2)) == 0); k=4: ((lane&1)==0);
    // k=2: per-register-pair.
    {
        // k = 2
        CMPX(0, 1, true)  CMPX(2, 3, false)
        // k = 4
        { const bool A = ((lane & 1) == 0);
          CMPX(0, 2, A) CMPX(1, 3, A) CMPX(0, 1, A) CMPX(2, 3, A) }
        // k = 8
        { const bool A = ((lane & 2) == 0);
          SHFL_ST(1, A)
          CMPX(0, 2, A) CMPX(1, 3, A) CMPX(0, 1, A) CMPX(2, 3, A) }
        // k = 16
        { const bool A = ((lane & 4) == 0);
          SHFL_ST(2, A) SHFL_ST(1, A)
          CMPX(0, 2, A) CMPX(1, 3, A) CMPX(0, 1, A) CMPX(2, 3, A) }
        // k = 32
        { const bool A = ((lane & 8) == 0);
          SHFL_ST(4, A) SHFL_ST(2, A) SHFL_ST(1, A)
          CMPX(0, 2, A) CMPX(1, 3, A) CMPX(0, 1, A) CMPX(2, 3, A) }
        // k = 64
        { const bool A = ((lane & 16) == 0);
          SHFL_ST(8, A) SHFL_ST(4, A) SHFL_ST(2, A) SHFL_ST(1, A)
          CMPX(0, 2, A) CMPX(1, 3, A) CMPX(0, 1, A) CMPX(2, 3, A) }
        // k = 128
        { const bool A = ((wg & 1) == 0);
          SHFL_ST(16, A) SHFL_ST(8, A) SHFL_ST(4, A) SHFL_ST(2, A) SHFL_ST(1, A)
          CMPX(0, 2, A) CMPX(1, 3, A) CMPX(0, 1, A) CMPX(2, 3, A) }
        // k = 256
        { const bool A = ((wg & 2) == 0);
          SMEM_ST(32, A, 0)
          SHFL_ST(16, A) SHFL_ST(8, A) SHFL_ST(4, A) SHFL_ST(2, A) SHFL_ST(1, A)
          CMPX(0, 2, A) CMPX(1, 3, A) CMPX(0, 1, A) CMPX(2, 3, A) }
        // k = 512 (ascending everywhere)
        {
          SMEM_ST(64, true, 1)
          SMEM_ST(32, true, 1)
          SHFL_ST(16, true) SHFL_ST(8, true) SHFL_ST(4, true)
          SHFL_ST(2, true)  SHFL_ST(1, true)
          CMPX(0, 2, true) CMPX(1, 3, true) CMPX(0, 1, true) CMPX(2, 3, true)
        }
    }

    // ---- pass 1: per-thread negative (sum, count), warp scan, group offsets --
    float runs = 0.f;
    int   runc = 0;
#pragma unroll
    for (int r = 0; r < 4; r++) {
        const bool isneg = ((__float_as_uint(v[r]) & 1u) == 0) && (v[r] < SENTTH);
        if (isneg) { runs += v[r]; runc++; }
    }
    float ls = runs;
    int   lc = runc;
#pragma unroll
    for (int off = 1; off < 32; off <<= 1) {
        const float y = __shfl_up_sync(FULLM, ls, off);
        const int   z = __shfl_up_sync(FULLM, lc, off);
        if (lane >= off) { ls += y; lc += z; }
    }
    // warp totals + per-warp npos/nneg
    {
        const float wts = __shfl_sync(FULLM, ls, 31);
        const int   wtc = __shfl_sync(FULLM, lc, 31);
        const int wnp = __reduce_add_sync(FULLM, npos);
        const int wnn = __reduce_add_sync(FULLM, nneg);
        if (lane == 0) {
            s_wt[g * 4 + wg] = wts;
            s_wc[g * 4 + wg] = wtc;
            s_np[g * 4 + wg] = wnp;
            s_nn[g * 4 + wg] = wnn;
        }
    }
    GBAR();
    float gs = 0.f;
    int   gc = 0;
#pragma unroll
    for (int w = 0; w < 4; w++) {
        if (w < wg) { gs += s_wt[g * 4 + w]; gc += s_wc[g * 4 + w]; }
    }
    float rs = gs + (ls - runs);   // exclusive prefix sum of negatives before e
    int   rc = gc + (lc - runc);

    // ---- pass 2: positive contributions along sorted order -------------------
    float local = 0.f;
#pragma unroll
    for (int r = 0; r < 4; r++) {
        const bool ispos = (__float_as_uint(v[r]) & 1u) != 0;
        if (ispos) {
            local += (float)rc * v[r] - rs;
        } else if (v[r] < SENTTH) {
            rs += v[r];
            rc++;
        }
    }
#pragma unroll
    for (int off = 16; off; off >>= 1)
        local += __shfl_down_sync(FULLM, local, off);
    if (lane == 0) s_bs[g * 4 + wg] = local;
    __syncthreads();

    if (tid == 0) {
        float s = 0.f;
        unsigned long long d = 0ull;
#pragma unroll
        for (int gg = 0; gg < 4; gg++) {
            int np = 0, nn = 0;
#pragma unroll
            for (int w = 0; w < 4; w++) {
                s  += s_bs[gg * 4 + w];
                np += s_np[gg * 4 + w];
                nn += s_nn[gg * 4 + w];
            }
            d += (unsigned long long)np * (unsigned long long)nn;
        }
        atomicAdd(&g_num, (double)s);
        atomicAdd(&g_den, d);
        __threadfence();
        const unsigned int ticket = atomicAdd(&g_done, 1u);
        if (ticket == gridDim.x - 1) {
            const double num = atomicAdd(&g_num, 0.0);
            const unsigned long long den = atomicAdd(&g_den, 0ull);
            out[0] = (den > 0ull) ? (float)(num / (double)den) : 0.0f;
            g_num  = 0.0;
            g_den  = 0ull;
            __threadfence();
            g_done = 0u;
        }
    }
}

// ---------------------------------------------------------------------------
extern "C" void kernel_launch(void* const* d_in, const int* in_sizes, int n_in,
                              void* d_out, int out_size) {
    const float* features = (const float*)d_in[0];   // [512,128] f32
    const int*   mask     = (const int*)d_in[1];     // [512,512] i32
    float* out = (float*)d_out;

    const int smem_bytes =
        (4 * LDJ + TJ * LDJ + 4 * LDD + 4 + 256 * 6 + 16 + 16) * (int)sizeof(float)
        + (16 + 16 + 16) * (int)sizeof(int);
    static bool attr_set = false;
    if (!attr_set) {
        cudaFuncSetAttribute(fused_kernel, cudaFuncAttributeMaxDynamicSharedMemorySize,
                             smem_bytes);
        attr_set = true;
    }

    fused_kernel<<<B / 4, NT, smem_bytes>>>(features, mask, out);
}

// round 16
// speedup vs baseline: 1.3795x; 1.0171x over previous
#include <cuda_runtime.h>
#include <cuda_bf16.h>
#include <cstdint>

#define B      512
#define DIM    128
#define MARGIN 0.2f
#define EPSF   1e-6f
#define BIGF   1e30f
#define SENTTH 1e29f
#define FULLM  0xffffffffu

#define LDU 132    // u row stride (floats)
#define LDC 68     // Fj column stride (floats): 64 dims + 4 pad (272B ≡ 16 mod 128)
#define LDD 516    // D slab row stride (floats)
#define NT  512

__device__ double g_num = 0.0;
__device__ unsigned long long g_den = 0ull;
__device__ unsigned int g_done = 0u;

static __device__ __forceinline__ unsigned smem_u32(const void* p) {
    return (unsigned)__cvta_generic_to_shared(p);
}
#define FMA2(acc, a, b) \
    asm volatile("fma.rn.f32x2 %0, %1, %2, %0;" : "+l"(acc) : "l"(a), "l"(b))
#define LDS_V2B64(lo, hi, addr) \
    asm volatile("ld.shared.v2.b64 {%0, %1}, [%2];" : "=l"(lo), "=l"(hi) : "r"(addr))
static __device__ __forceinline__ float hadd_f32x2(uint64_t p) {
    float lo, hi;
    asm volatile("mov.b64 {%0, %1}, %2;" : "=f"(lo), "=f"(hi) : "l"(p));
    return lo + hi;
}

// ---- 4-warp cooperative bitonic helpers (group = 128 threads, 4 keys/thread)
#define GBAR() asm volatile("bar.sync %0, 128;" :: "r"(g + 1) : "memory")

#define CMPX(a, b, ASC) {                                                     \
    const float lo = fminf(v[a], v[b]), hi = fmaxf(v[a], v[b]);               \
    v[a] = (ASC) ? lo : hi; v[b] = (ASC) ? hi : lo; }

#define SHFL_ST(JL, ASC) {                                                    \
    const bool km = (((lane & (JL)) == 0) == (ASC));                          \
    _Pragma("unroll")                                                         \
    for (int r = 0; r < 4; r++) {                                             \
        const float p = __shfl_xor_sync(FULLM, v[r], (JL));                   \
        v[r] = km ? fminf(v[r], p) : fmaxf(v[r], p);                          \
    } }

#define SMEM_ST(JT, ASC, LEAD) {                                              \
    if (LEAD) GBAR();                                                         \
    *(float4*)&D_s[g * LDD + t * 4] = make_float4(v[0], v[1], v[2], v[3]);    \
    GBAR();                                                                   \
    const float4 pv = *(const float4*)&D_s[g * LDD + (t ^ (JT)) * 4];         \
    const bool km = (((t & (JT)) == 0) == (ASC));                             \
    v[0] = km ? fminf(v[0], pv.x) : fmaxf(v[0], pv.x);                        \
    v[1] = km ? fminf(v[1], pv.y) : fmaxf(v[1], pv.y);                        \
    v[2] = km ? fminf(v[2], pv.z) : fmaxf(v[2], pv.z);                        \
    v[3] = km ? fminf(v[3], pv.w) : fmaxf(v[3], pv.w); }

// ---------------------------------------------------------------------------
// ONE fused kernel, 512 threads. Block b = anchor rows [4b, 4b+4).
// Phase A: 2 d-tiles of 64 dims covering ALL 512 j-columns (139KB buffer).
//   Thread tid owns column tid for all 4 anchors; accumulates the full dot in
//   registers across both tiles — NO cross-thread combine phase.
// Phase B: ALL 16 warps; group g of 4 warps cooperatively sorts row i0+g
//   (R15-verified), closed-form triplet sum, single atomic finalize.
// ---------------------------------------------------------------------------
__global__ __launch_bounds__(NT) void fused_kernel(const float* __restrict__ F,
                                                   const int* __restrict__ mask,
                                                   float* __restrict__ out) {
    extern __shared__ float sm[];
    float* u_s  = sm;                          //   4 * 132
    float* Fc_s = u_s + 4 * LDU;               // 512 * 68
    float* D_s  = Fc_s + B * LDC;              //   4 * 516 (also sort scratch)
    float* s_ni = D_s + 4 * LDD;               //   4
    float* s_wt = s_ni + 4;                    //  16
    int*   s_wc = (int*)(s_wt + 16);           //  16
    int*   s_np = s_wc + 16;                   //  16
    int*   s_nn = s_np + 16;                   //  16
    float* s_bs = (float*)(s_nn + 16);         //  16

    const int tid  = threadIdx.x;
    const int lane = tid & 31;
    const int warp = tid >> 5;
    const int i0   = blockIdx.x * 4;
    const int g    = warp >> 2;       // sort group = row
    const int wg   = warp & 3;        // warp within group
    const int t    = wg * 32 + lane;  // thread index within group

    // ---- prefetch mask quad for my sort elements -----------------------------
    const int4 m4 = ((const int4*)(mask + (i0 + g) * B))[t];

    // ---- stage u = f(anchor rows) + eps (1 elem/thread) ----------------------
    {
        const int r = tid >> 7, d = tid & 127;
        u_s[r * LDU + d] = F[(i0 + r) * DIM + d] + EPSF;
    }
    __syncthreads();

    // ---- |u_i|^2 (warps 0-3; warp w -> row w) --------------------------------
    if (warp < 4) {
        float s = 0.f;
#pragma unroll
        for (int qq = 0; qq < 4; qq++) {
            const float x = u_s[warp * LDU + lane + 32 * qq];
            s = fmaf(x, x, s);
        }
#pragma unroll
        for (int off = 16; off; off >>= 1) s += __shfl_down_sync(FULLM, s, off);
        if (lane == 0) s_ni[warp] = s;
    }

    const float4* F4 = (const float4*)F;
    const unsigned ub  = smem_u32(u_s);
    const unsigned fb  = smem_u32(Fc_s) + (unsigned)tid * LDC * 4u;

    // ---- Phase A: 2 d-tiles of 64 dims, all 512 columns ----------------------
    uint64_t A0 = 0ull, A1 = 0ull, A2 = 0ull, A3 = 0ull, NF2 = 0ull;

#pragma unroll
    for (int hp = 0; hp < 2; hp++) {
        if (hp) __syncthreads();   // protect Fc_s reuse across d-tiles
        // stage: 512 rows x 16 float4 (dims [64hp, 64hp+64)), 16 per thread
#pragma unroll
        for (int k = 0; k < 16; k++) {
            const int gidx = tid + (k << 9);
            const int row = gidx >> 4, sub = gidx & 15;
            const float4 fv = F4[row * 32 + 16 * hp + sub];
            *(float4*)&Fc_s[row * LDC + sub * 4] = fv;
        }
        __syncthreads();

        const unsigned u0a = ub + (0 * LDU + 64 * hp) * 4u;
        const unsigned u1a = ub + (1 * LDU + 64 * hp) * 4u;
        const unsigned u2a = ub + (2 * LDU + 64 * hp) * 4u;
        const unsigned u3a = ub + (3 * LDU + 64 * hp) * 4u;
#pragma unroll
        for (int dq = 0; dq < 16; dq++) {
            uint64_t f0, f1, x0, x1;
            LDS_V2B64(f0, f1, fb + 16 * dq);
            FMA2(NF2, f0, f0);
            FMA2(NF2, f1, f1);
            LDS_V2B64(x0, x1, u0a + 16 * dq);
            FMA2(A0, x0, f0);
            FMA2(A0, x1, f1);
            LDS_V2B64(x0, x1, u1a + 16 * dq);
            FMA2(A1, x0, f0);
            FMA2(A1, x1, f1);
            LDS_V2B64(x0, x1, u2a + 16 * dq);
            FMA2(A2, x0, f0);
            FMA2(A2, x1, f1);
            LDS_V2B64(x0, x1, u3a + 16 * dq);
            FMA2(A3, x0, f0);
            FMA2(A3, x1, f1);
        }
    }

    // ---- epilogue: D row slab (thread owns column tid, no combine) -----------
    {
        const float a0 = hadd_f32x2(A0);
        const float a1 = hadd_f32x2(A1);
        const float a2 = hadd_f32x2(A2);
        const float a3 = hadd_f32x2(A3);
        const float nf = hadd_f32x2(NF2);
        D_s[0 * LDD + tid] = sqrtf(fmaxf(s_ni[0] + nf - 2.f * a0, 0.f));
        D_s[1 * LDD + tid] = sqrtf(fmaxf(s_ni[1] + nf - 2.f * a1, 0.f));
        D_s[2 * LDD + tid] = sqrtf(fmaxf(s_ni[2] + nf - 2.f * a2, 0.f));
        D_s[3 * LDD + tid] = sqrtf(fmaxf(s_ni[3] + nf - 2.f * a3, 0.f));
    }
    __syncthreads();   // D_s complete

    // =========================================================================
    // Phase B: ALL 16 warps. Group g (4 warps) sorts row i0+g cooperatively.
    // Thread owns elements e = t*4 + r. LSB tag; sentinel value-guarded.
    // (Verified R15.)
    // =========================================================================
    float v[4];
    int npos = 0, nneg = 0;
    {
        const float4 d4 = *(const float4*)&D_s[g * LDD + t * 4];
        const float dv[4] = {d4.x, d4.y, d4.z, d4.w};
        const int   mv[4] = {m4.x, m4.y, m4.z, m4.w};
        const int   i     = i0 + g;
#pragma unroll
        for (int r = 0; r < 4; r++) {
            const int j = t * 4 + r;
            unsigned kb;
            if (mv[r] != 0) {
                kb = __float_as_uint(dv[r] + MARGIN) | 1u;
                npos++;
            } else if (j == i) {
                kb = __float_as_uint(BIGF) & ~1u;
            } else {
                kb = __float_as_uint(dv[r]) & ~1u;
                nneg++;
            }
            v[r] = __uint_as_float(kb);
        }
    }

    // ---- cooperative bitonic sort, ascending over e = t*4 + r ---------------
    {
        // k = 2
        CMPX(0, 1, true)  CMPX(2, 3, false)
        // k = 4
        { const bool A = ((lane & 1) == 0);
          CMPX(0, 2, A) CMPX(1, 3, A) CMPX(0, 1, A) CMPX(2, 3, A) }
        // k = 8
        { const bool A = ((lane & 2) == 0);
          SHFL_ST(1, A)
          CMPX(0, 2, A) CMPX(1, 3, A) CMPX(0, 1, A) CMPX(2, 3, A) }
        // k = 16
        { const bool A = ((lane & 4) == 0);
          SHFL_ST(2, A) SHFL_ST(1, A)
          CMPX(0, 2, A) CMPX(1, 3, A) CMPX(0, 1, A) CMPX(2, 3, A) }
        // k = 32
        { const bool A = ((lane & 8) == 0);
          SHFL_ST(4, A) SHFL_ST(2, A) SHFL_ST(1, A)
          CMPX(0, 2, A) CMPX(1, 3, A) CMPX(0, 1, A) CMPX(2, 3, A) }
        // k = 64
        { const bool A = ((lane & 16) == 0);
          SHFL_ST(8, A) SHFL_ST(4, A) SHFL_ST(2, A) SHFL_ST(1, A)
          CMPX(0, 2, A) CMPX(1, 3, A) CMPX(0, 1, A) CMPX(2, 3, A) }
        // k = 128
        { const bool A = ((wg & 1) == 0);
          SHFL_ST(16, A) SHFL_ST(8, A) SHFL_ST(4, A) SHFL_ST(2, A) SHFL_ST(1, A)
          CMPX(0, 2, A) CMPX(1, 3, A) CMPX(0, 1, A) CMPX(2, 3, A) }
        // k = 256
        { const bool A = ((wg & 2) == 0);
          SMEM_ST(32, A, 0)
          SHFL_ST(16, A) SHFL_ST(8, A) SHFL_ST(4, A) SHFL_ST(2, A) SHFL_ST(1, A)
          CMPX(0, 2, A) CMPX(1, 3, A) CMPX(0, 1, A) CMPX(2, 3, A) }
        // k = 512 (ascending everywhere)
        {
          SMEM_ST(64, true, 1)
          SMEM_ST(32, true, 1)
          SHFL_ST(16, true) SHFL_ST(8, true) SHFL_ST(4, true)
          SHFL_ST(2, true)  SHFL_ST(1, true)
          CMPX(0, 2, true) CMPX(1, 3, true) CMPX(0, 1, true) CMPX(2, 3, true)
        }
    }

    // ---- pass 1: negative (sum, count) scan across the group -----------------
    float runs = 0.f;
    int   runc = 0;
#pragma unroll
    for (int r = 0; r < 4; r++) {
        const bool isneg = ((__float_as_uint(v[r]) & 1u) == 0) && (v[r] < SENTTH);
        if (isneg) { runs += v[r]; runc++; }
    }
    float ls = runs;
    int   lc = runc;
#pragma unroll
    for (int off = 1; off < 32; off <<= 1) {
        const float y = __shfl_up_sync(FULLM, ls, off);
        const int   z = __shfl_up_sync(FULLM, lc, off);
        if (lane >= off) { ls += y; lc += z; }
    }
    {
        const float wts = __shfl_sync(FULLM, ls, 31);
        const int   wtc = __shfl_sync(FULLM, lc, 31);
        const int wnp = __reduce_add_sync(FULLM, npos);
        const int wnn = __reduce_add_sync(FULLM, nneg);
        if (lane == 0) {
            s_wt[g * 4 + wg] = wts;
            s_wc[g * 4 + wg] = wtc;
            s_np[g * 4 + wg] = wnp;
            s_nn[g * 4 + wg] = wnn;
        }
    }
    GBAR();
    float gs = 0.f;
    int   gc = 0;
#pragma unroll
    for (int w = 0; w < 4; w++) {
        if (w < wg) { gs += s_wt[g * 4 + w]; gc += s_wc[g * 4 + w]; }
    }
    float rs = gs + (ls - runs);
    int   rc = gc + (lc - runc);

    // ---- pass 2: positive contributions along sorted order -------------------
    float local = 0.f;
#pragma unroll
    for (int r = 0; r < 4; r++) {
        const bool ispos = (__float_as_uint(v[r]) & 1u) != 0;
        if (ispos) {
            local += (float)rc * v[r] - rs;
        } else if (v[r] < SENTTH) {
            rs += v[r];
            rc++;
        }
    }
#pragma unroll
    for (int off = 16; off; off >>= 1)
        local += __shfl_down_sync(FULLM, local, off);
    if (lane == 0) s_bs[g * 4 + wg] = local;
    __syncthreads();

    if (tid == 0) {
        float s = 0.f;
        unsigned long long d = 0ull;
#pragma unroll
        for (int gg = 0; gg < 4; gg++) {
            int np = 0, nn = 0;
#pragma unroll
            for (int w = 0; w < 4; w++) {
                s  += s_bs[gg * 4 + w];
                np += s_np[gg * 4 + w];
                nn += s_nn[gg * 4 + w];
            }
            d += (unsigned long long)np * (unsigned long long)nn;
        }
        atomicAdd(&g_num, (double)s);
        atomicAdd(&g_den, d);
        __threadfence();
        const unsigned int ticket = atomicAdd(&g_done, 1u);
        if (ticket == gridDim.x - 1) {
            const double num = atomicAdd(&g_num, 0.0);
            const unsigned long long den = atomicAdd(&g_den, 0ull);
            out[0] = (den > 0ull) ? (float)(num / (double)den) : 0.0f;
            g_num  = 0.0;
            g_den  = 0ull;
            __threadfence();
            g_done = 0u;
        }
    }
}

// ---------------------------------------------------------------------------
extern "C" void kernel_launch(void* const* d_in, const int* in_sizes, int n_in,
                              void* d_out, int out_size) {
    const float* features = (const float*)d_in[0];   // [512,128] f32
    const int*   mask     = (const int*)d_in[1];     // [512,512] i32
    float* out = (float*)d_out;

    const int smem_bytes =
        (4 * LDU + B * LDC + 4 * LDD + 4 + 16 + 16) * (int)sizeof(float)
        + (16 + 16 + 16) * (int)sizeof(int);
    static bool attr_set = false;
    if (!attr_set) {
        cudaFuncSetAttribute(fused_kernel, cudaFuncAttributeMaxDynamicSharedMemorySize,
                             smem_bytes);
        attr_set = true;
    }

    fused_kernel<<<B / 4, NT, smem_bytes>>>(features, mask, out);
}